// round 2
// baseline (speedup 1.0000x reference)
#include <cuda_runtime.h>
#include <cuda_bf16.h>

// Problem constants
#define BB 4
#define HH 8
#define NN 4096
#define DD 64
#define RR 256
#define BH (BB*HH)
#define SCALE 0.35355339059327373f   // 64^(-1/4)
#define EPS 0.001f

#define SPLIT_A 16   // blocks per (b,h) in pass A  -> 512 blocks, 256 rows each
#define SPLIT_B 16   // blocks per (b,h) in pass B  -> 512 blocks, 256 rows each

// Scratch: context[BH][R][D] and ksum[BH][R]
__device__ float g_ctx[BH * RR * DD];    // 2 MB
__device__ float g_ksum[BH * RR];        // 32 KB

// ---------------------------------------------------------------------------
// Kernel 0: zero the scratch (required each launch; graph replays)
// ---------------------------------------------------------------------------
__global__ void zero_kernel() {
    int i = blockIdx.x * blockDim.x + threadIdx.x;
    if (i < BH * RR * DD) g_ctx[i] = 0.0f;
    if (i < BH * RR)      g_ksum[i] = 0.0f;
}

// ---------------------------------------------------------------------------
// Pass A: phi_k = relu(K*scale*m @ proj^T)+eps ; accumulate
//         ksum[r] += phi_k[n][r] ; ctx[r][d] += phi_k[n][r]*v[n][d]
// Thread t owns feature r=t. proj row and ctx row live in registers.
// ---------------------------------------------------------------------------
__global__ void __launch_bounds__(256) passA_kernel(
    const float* __restrict__ Kg, const float* __restrict__ Vg,
    const float* __restrict__ maskg, const float* __restrict__ projg)
{
    __shared__ __align__(16) float ks[8][64];
    __shared__ __align__(16) float vs[8][64];

    const int t = threadIdx.x;
    const int bh    = blockIdx.x >> 4;      // SPLIT_A = 16
    const int chunk = blockIdx.x & 15;
    const int b     = bh >> 3;              // H = 8
    const int row0  = chunk * (NN / SPLIT_A);   // 256 rows per block

    const float* Kp = Kg + ((size_t)bh * NN + row0) * DD;
    const float* Vp = Vg + ((size_t)bh * NN + row0) * DD;
    const float* mp = maskg + (size_t)b * NN + row0;

    // proj column for this thread's feature (proj is [R][D] row-major)
    float pc[64];
    #pragma unroll
    for (int i = 0; i < 16; ++i) {
        float4 p = reinterpret_cast<const float4*>(projg)[t * 16 + i];
        pc[4*i+0] = p.x; pc[4*i+1] = p.y; pc[4*i+2] = p.z; pc[4*i+3] = p.w;
    }

    float ctx[64];
    #pragma unroll
    for (int d = 0; d < 64; ++d) ctx[d] = 0.0f;
    float ksacc = 0.0f;

    const int nrows = NN / SPLIT_A;        // 256
    const int ntiles = nrows / 8;          // 32

    for (int tile = 0; tile < ntiles; ++tile) {
        __syncthreads();
        // load 8 rows of K and V (1024 floats), 1 float4 per thread
        {
            if (t < 128) {
                int rr = t >> 4;
                int d  = (t & 15) * 4;
                float m  = mp[tile * 8 + rr];
                float sm = SCALE * m;
                float4 kv = *reinterpret_cast<const float4*>(Kp + (tile*8 + rr)*64 + d);
                ks[rr][d+0] = kv.x * sm; ks[rr][d+1] = kv.y * sm;
                ks[rr][d+2] = kv.z * sm; ks[rr][d+3] = kv.w * sm;
            } else {
                int u  = t - 128;
                int rr = u >> 4;
                int d  = (u & 15) * 4;
                float m  = mp[tile * 8 + rr];
                float4 vv = *reinterpret_cast<const float4*>(Vp + (tile*8 + rr)*64 + d);
                vs[rr][d+0] = vv.x * m; vs[rr][d+1] = vv.y * m;
                vs[rr][d+2] = vv.z * m; vs[rr][d+3] = vv.w * m;
            }
        }
        __syncthreads();

        #pragma unroll 1
        for (int rr = 0; rr < 8; ++rr) {
            float a0 = 0.f, a1 = 0.f, a2 = 0.f, a3 = 0.f;
            #pragma unroll
            for (int i = 0; i < 16; ++i) {
                float4 kk = *reinterpret_cast<const float4*>(&ks[rr][4*i]);
                a0 = fmaf(kk.x, pc[4*i+0], a0);
                a1 = fmaf(kk.y, pc[4*i+1], a1);
                a2 = fmaf(kk.z, pc[4*i+2], a2);
                a3 = fmaf(kk.w, pc[4*i+3], a3);
            }
            float phi = fmaxf((a0 + a1) + (a2 + a3), 0.0f) + EPS;
            ksacc += phi;
            #pragma unroll
            for (int i = 0; i < 16; ++i) {
                float4 vv = *reinterpret_cast<const float4*>(&vs[rr][4*i]);
                ctx[4*i+0] = fmaf(phi, vv.x, ctx[4*i+0]);
                ctx[4*i+1] = fmaf(phi, vv.y, ctx[4*i+1]);
                ctx[4*i+2] = fmaf(phi, vv.z, ctx[4*i+2]);
                ctx[4*i+3] = fmaf(phi, vv.w, ctx[4*i+3]);
            }
        }
    }

    // accumulate partials into global scratch
    float* gc = g_ctx + ((size_t)bh * RR + t) * DD;
    #pragma unroll
    for (int d = 0; d < 64; ++d) atomicAdd(gc + d, ctx[d]);
    atomicAdd(g_ksum + bh * RR + t, ksacc);
}

// ---------------------------------------------------------------------------
// Pass B: phi_q = relu(Q*scale @ proj^T)+eps ;
//         out[n][d] = (phi_q[n] . ctx[:,d]) / (phi_q[n] . ksum)
// Dynamic shared layout (floats):
//   ctx_s  [256*64]  @ 0
//   ksum_s [256]     @ 16384
//   qs     [64*64]   @ 16640
//   phi_s  [64*257]  @ 20736   (stride 257 -> conflict-free)
// total = 37184 floats = 148736 bytes
// ---------------------------------------------------------------------------
#define SMEM_B_FLOATS 37184
#define SMEM_B_BYTES  (SMEM_B_FLOATS * 4)

__global__ void __launch_bounds__(256) passB_kernel(
    const float* __restrict__ Qg, const float* __restrict__ projg,
    float* __restrict__ outg)
{
    extern __shared__ float smem[];
    float* ctx_s  = smem;            // 16384
    float* ksum_s = smem + 16384;    // 256
    float* qs     = smem + 16640;    // 4096
    float* phi_s  = smem + 20736;    // 64*257

    const int t = threadIdx.x;
    const int bh    = blockIdx.x >> 4;     // SPLIT_B = 16
    const int chunk = blockIdx.x & 15;
    const int row0  = chunk * (NN / SPLIT_B);   // 256

    // load context + ksum for this bh
    const float* gc = g_ctx + (size_t)bh * RR * DD;
    for (int i = t; i < RR * DD; i += 256) ctx_s[i] = gc[i];
    ksum_s[t] = g_ksum[bh * RR + t];

    // proj column for feature t
    float pc[64];
    #pragma unroll
    for (int i = 0; i < 16; ++i) {
        float4 p = reinterpret_cast<const float4*>(projg)[t * 16 + i];
        pc[4*i+0] = p.x; pc[4*i+1] = p.y; pc[4*i+2] = p.z; pc[4*i+3] = p.w;
    }
    __syncthreads();

    const float* Qp = Qg  + ((size_t)bh * NN + row0) * DD;
    float*       Op = outg + ((size_t)bh * NN + row0) * DD;

    const int g  = t >> 2;   // output row within tile (0..63)
    const int td = t & 3;    // d-quarter (16 cols each)

    const int ntiles = (NN / SPLIT_B) / 64;   // 4 tiles of 64 rows

    for (int tile = 0; tile < ntiles; ++tile) {
        // load 64x64 Q tile (pre-scaled), 4 float4 per thread
        {
            const float4* Q4 = reinterpret_cast<const float4*>(Qp + (size_t)tile * 64 * 64);
            float4* qs4 = reinterpret_cast<float4*>(qs);
            #pragma unroll
            for (int i = 0; i < 4; ++i) {
                float4 q = Q4[t + i * 256];
                q.x *= SCALE; q.y *= SCALE; q.z *= SCALE; q.w *= SCALE;
                qs4[t + i * 256] = q;
            }
        }
        __syncthreads();

        // stage 1: thread t computes phi[g2][t] for all 64 rows
        #pragma unroll 1
        for (int g2 = 0; g2 < 64; ++g2) {
            float a0 = 0.f, a1 = 0.f, a2 = 0.f, a3 = 0.f;
            const float4* qrow = reinterpret_cast<const float4*>(qs + g2 * 64);
            #pragma unroll
            for (int i = 0; i < 16; ++i) {
                float4 qq = qrow[i];
                a0 = fmaf(qq.x, pc[4*i+0], a0);
                a1 = fmaf(qq.y, pc[4*i+1], a1);
                a2 = fmaf(qq.z, pc[4*i+2], a2);
                a3 = fmaf(qq.w, pc[4*i+3], a3);
            }
            phi_s[g2 * 257 + t] = fmaxf((a0 + a1) + (a2 + a3), 0.0f) + EPS;
        }
        __syncthreads();

        // stage 2: thread computes out[g][td*16 .. td*16+15] and its own d_inv
        float acc[16];
        #pragma unroll
        for (int i = 0; i < 16; ++i) acc[i] = 0.0f;
        float dsum = 0.0f;

        const float* phrow = phi_s + g * 257;
        const float4* c4 = reinterpret_cast<const float4*>(ctx_s);
        #pragma unroll 2
        for (int r = 0; r < RR; ++r) {
            float ph = phrow[r];
            dsum = fmaf(ph, ksum_s[r], dsum);
            #pragma unroll
            for (int i = 0; i < 4; ++i) {
                float4 c = c4[r * 16 + td * 4 + i];
                acc[4*i+0] = fmaf(ph, c.x, acc[4*i+0]);
                acc[4*i+1] = fmaf(ph, c.y, acc[4*i+1]);
                acc[4*i+2] = fmaf(ph, c.z, acc[4*i+2]);
                acc[4*i+3] = fmaf(ph, c.w, acc[4*i+3]);
            }
        }
        float rinv = 1.0f / dsum;

        // write output row segment
        {
            float4* O4 = reinterpret_cast<float4*>(Op);
            #pragma unroll
            for (int i = 0; i < 4; ++i) {
                float4 o;
                o.x = acc[4*i+0] * rinv;
                o.y = acc[4*i+1] * rinv;
                o.z = acc[4*i+2] * rinv;
                o.w = acc[4*i+3] * rinv;
                O4[(size_t)(tile * 64 + g) * 16 + td * 4 + i] = o;
            }
        }
        __syncthreads();   // protect qs/phi_s before next tile overwrites
    }
}

// ---------------------------------------------------------------------------
// Launch
// ---------------------------------------------------------------------------
extern "C" void kernel_launch(void* const* d_in, const int* in_sizes, int n_in,
                              void* d_out, int out_size)
{
    const float* Q    = (const float*)d_in[0];
    const float* K    = (const float*)d_in[1];
    const float* V    = (const float*)d_in[2];
    const float* mask = (const float*)d_in[3];
    const float* proj = (const float*)d_in[4];
    float* out = (float*)d_out;

    cudaFuncSetAttribute(passB_kernel,
                         cudaFuncAttributeMaxDynamicSharedMemorySize,
                         SMEM_B_BYTES);

    zero_kernel<<<(BH * RR * DD) / 256, 256>>>();
    passA_kernel<<<BH * SPLIT_A, 256>>>(K, V, mask, proj);
    passB_kernel<<<BH * SPLIT_B, 256, SMEM_B_BYTES>>>(Q, proj, out);
}

// round 6
// speedup vs baseline: 1.0671x; 1.0671x over previous
#include <cuda_runtime.h>
#include <cuda_bf16.h>

// Problem constants
#define BB 4
#define HH 8
#define NN 4096
#define DD 64
#define RR 256
#define BH (BB*HH)
#define SCALE 0.35355339059327373f   // 64^(-1/4)
#define EPS 0.001f

#define SPLIT_A 16   // blocks per (b,h) in pass A  -> 512 blocks, 256 rows each
#define SPLIT_B 16   // blocks per (b,h) in pass B  -> 512 blocks, 256 rows each

typedef unsigned long long u64t;

// packed fp32x2 helpers (sm_100+): one issue = 2 fp32 FMAs
__device__ __forceinline__ u64t pack2f(float x, float y) {
    u64t r;
    asm("mov.b64 %0, {%1, %2};" : "=l"(r) : "f"(x), "f"(y));
    return r;
}
__device__ __forceinline__ void unpack2f(u64t u, float& x, float& y) {
    asm("mov.b64 {%0, %1}, %2;" : "=f"(x), "=f"(y) : "l"(u));
}
__device__ __forceinline__ void ffma2(u64t& d, u64t a, u64t b) {
    asm("fma.rn.f32x2 %0, %1, %2, %3;" : "=l"(d) : "l"(a), "l"(b), "l"(d));
}

// Scratch: context[BH][R][D] and ksum[BH][R]
__device__ float g_ctx[BH * RR * DD];    // 2 MB
__device__ float g_ksum[BH * RR];        // 32 KB

// ---------------------------------------------------------------------------
// Kernel 0: zero the scratch (graph replays require re-zeroing)
// ---------------------------------------------------------------------------
__global__ void zero_kernel() {
    int i = blockIdx.x * blockDim.x + threadIdx.x;
    if (i < BH * RR * DD) g_ctx[i] = 0.0f;
    if (i < BH * RR)      g_ksum[i] = 0.0f;
}

// ---------------------------------------------------------------------------
// Pass A: phi_k = relu(K*scale*m @ proj^T)+eps ; accumulate
//         ksum[r] += phi_k[n][r] ; ctx[r][d] += phi_k[n][r]*v[n][d]
// Thread t owns feature r=t. 16-row double-buffered tiles, packed FFMA2.
// ---------------------------------------------------------------------------
__global__ void __launch_bounds__(256) passA_kernel(
    const float* __restrict__ Kg, const float* __restrict__ Vg,
    const float* __restrict__ maskg, const float* __restrict__ projg)
{
    __shared__ __align__(16) float ks[2][16][64];   // 8 KB x2
    __shared__ __align__(16) float vs[2][16][64];   // 8 KB x2

    const int t = threadIdx.x;
    const int bh    = blockIdx.x >> 4;      // SPLIT_A = 16
    const int chunk = blockIdx.x & 15;
    const int b     = bh >> 3;              // H = 8
    const int row0  = chunk * (NN / SPLIT_A);   // 256 rows per block

    const float* Kp = Kg + ((size_t)bh * NN + row0) * DD;
    const float* Vp = Vg + ((size_t)bh * NN + row0) * DD;
    const float* mp = maskg + (size_t)b * NN + row0;

    // proj column for this thread's feature, packed as 32 x f32x2
    u64t pc2[32];
    #pragma unroll
    for (int i = 0; i < 16; ++i) {
        float4 p = reinterpret_cast<const float4*>(projg)[t * 16 + i];
        pc2[2*i+0] = pack2f(p.x, p.y);
        pc2[2*i+1] = pack2f(p.z, p.w);
    }

    u64t ctx2[32];
    #pragma unroll
    for (int i = 0; i < 32; ++i) ctx2[i] = 0ull;
    float ksacc = 0.0f;

    const int lrow = t >> 4;         // 0..15 (row within tile)
    const int lcol = (t & 15) * 4;   // 0..60 (float4 column)

    // load tile 0 into buffer 0
    {
        float m  = mp[lrow];
        float sm = SCALE * m;
        float4 kk = *reinterpret_cast<const float4*>(Kp + lrow * 64 + lcol);
        float4 vv = *reinterpret_cast<const float4*>(Vp + lrow * 64 + lcol);
        ks[0][lrow][lcol+0] = kk.x * sm; ks[0][lrow][lcol+1] = kk.y * sm;
        ks[0][lrow][lcol+2] = kk.z * sm; ks[0][lrow][lcol+3] = kk.w * sm;
        vs[0][lrow][lcol+0] = vv.x * m;  vs[0][lrow][lcol+1] = vv.y * m;
        vs[0][lrow][lcol+2] = vv.z * m;  vs[0][lrow][lcol+3] = vv.w * m;
    }
    __syncthreads();

    const int ntiles = (NN / SPLIT_A) / 16;   // 16 tiles of 16 rows
    int p = 0;

    for (int tile = 0; tile < ntiles; ++tile) {
        // prefetch next tile into registers (overlaps with compute below)
        float4 nk, nv; float nm = 0.0f;
        if (tile + 1 < ntiles) {
            int r = (tile + 1) * 16 + lrow;
            nk = *reinterpret_cast<const float4*>(Kp + r * 64 + lcol);
            nv = *reinterpret_cast<const float4*>(Vp + r * 64 + lcol);
            nm = mp[r];
        }

        // compute on buffer p
        #pragma unroll 1
        for (int rr = 0; rr < 16; ++rr) {
            u64t a0 = 0ull, a1 = 0ull;
            #pragma unroll
            for (int i = 0; i < 16; ++i) {
                float4 kk = *reinterpret_cast<const float4*>(&ks[p][rr][4*i]);
                u64t klo = pack2f(kk.x, kk.y);
                u64t khi = pack2f(kk.z, kk.w);
                ffma2(a0, klo, pc2[2*i+0]);
                ffma2(a1, khi, pc2[2*i+1]);
            }
            float x0, y0, x1, y1;
            unpack2f(a0, x0, y0);
            unpack2f(a1, x1, y1);
            float phi = fmaxf((x0 + y0) + (x1 + y1), 0.0f) + EPS;
            ksacc += phi;
            u64t phi2 = pack2f(phi, phi);
            #pragma unroll
            for (int i = 0; i < 16; ++i) {
                float4 vv = *reinterpret_cast<const float4*>(&vs[p][rr][4*i]);
                u64t vlo = pack2f(vv.x, vv.y);
                u64t vhi = pack2f(vv.z, vv.w);
                ffma2(ctx2[2*i+0], phi2, vlo);
                ffma2(ctx2[2*i+1], phi2, vhi);
            }
        }

        // store prefetched tile into the other buffer
        if (tile + 1 < ntiles) {
            int q = p ^ 1;
            float sm = SCALE * nm;
            ks[q][lrow][lcol+0] = nk.x * sm; ks[q][lrow][lcol+1] = nk.y * sm;
            ks[q][lrow][lcol+2] = nk.z * sm; ks[q][lrow][lcol+3] = nk.w * sm;
            vs[q][lrow][lcol+0] = nv.x * nm; vs[q][lrow][lcol+1] = nv.y * nm;
            vs[q][lrow][lcol+2] = nv.z * nm; vs[q][lrow][lcol+3] = nv.w * nm;
        }
        __syncthreads();
        p ^= 1;
    }

    // accumulate partials into global scratch
    float* gc = g_ctx + ((size_t)bh * RR + t) * DD;
    #pragma unroll
    for (int i = 0; i < 32; ++i) {
        float x, y;
        unpack2f(ctx2[i], x, y);
        atomicAdd(gc + 2*i + 0, x);
        atomicAdd(gc + 2*i + 1, y);
    }
    atomicAdd(g_ksum + bh * RR + t, ksacc);
}

// ---------------------------------------------------------------------------
// Pass B: phi_q = relu(Q*scale @ proj^T)+eps ;
//         out[n][d] = (phi_q[n] . ctx[:,d]) / (phi_q[n] . ksum)
// Dynamic shared layout (floats):
//   ctx_s  [256*64]  @ 0
//   ksum_s [256]     @ 16384
//   qs     [64*64]   @ 16640
//   phi_s  [64*257]  @ 20736   (stride 257 -> conflict-free)
// total = 37184 floats = 148736 bytes
// ---------------------------------------------------------------------------
#define SMEM_B_FLOATS 37184
#define SMEM_B_BYTES  (SMEM_B_FLOATS * 4)

__global__ void __launch_bounds__(256) passB_kernel(
    const float* __restrict__ Qg, const float* __restrict__ projg,
    float* __restrict__ outg)
{
    extern __shared__ float smem[];
    float* ctx_s  = smem;            // 16384
    float* ksum_s = smem + 16384;    // 256
    float* qs     = smem + 16640;    // 4096
    float* phi_s  = smem + 20736;    // 64*257

    const int t = threadIdx.x;
    const int bh    = blockIdx.x >> 4;     // SPLIT_B = 16
    const int chunk = blockIdx.x & 15;
    const int row0  = chunk * (NN / SPLIT_B);   // 256

    // load context + ksum for this bh
    const float* gc = g_ctx + (size_t)bh * RR * DD;
    for (int i = t; i < RR * DD; i += 256) ctx_s[i] = gc[i];
    ksum_s[t] = g_ksum[bh * RR + t];

    // proj column for feature t, packed
    u64t pc2[32];
    #pragma unroll
    for (int i = 0; i < 16; ++i) {
        float4 p = reinterpret_cast<const float4*>(projg)[t * 16 + i];
        pc2[2*i+0] = pack2f(p.x, p.y);
        pc2[2*i+1] = pack2f(p.z, p.w);
    }
    __syncthreads();

    const float* Qp = Qg  + ((size_t)bh * NN + row0) * DD;
    float*       Op = outg + ((size_t)bh * NN + row0) * DD;

    const int g  = t >> 2;   // output row within tile (0..63)
    const int td = t & 3;    // d-quarter (16 cols each)

    const int ntiles = (NN / SPLIT_B) / 64;   // 4 tiles of 64 rows

    for (int tile = 0; tile < ntiles; ++tile) {
        // load 64x64 Q tile (pre-scaled), 4 float4 per thread
        {
            const float4* Q4 = reinterpret_cast<const float4*>(Qp + (size_t)tile * 64 * 64);
            float4* qs4 = reinterpret_cast<float4*>(qs);
            #pragma unroll
            for (int i = 0; i < 4; ++i) {
                float4 q = Q4[t + i * 256];
                q.x *= SCALE; q.y *= SCALE; q.z *= SCALE; q.w *= SCALE;
                qs4[t + i * 256] = q;
            }
        }
        __syncthreads();

        // stage 1: thread t computes phi[g2][t] for all 64 rows (packed dot)
        #pragma unroll 1
        for (int g2 = 0; g2 < 64; ++g2) {
            u64t a0 = 0ull, a1 = 0ull;
            const float4* qrow = reinterpret_cast<const float4*>(qs + g2 * 64);
            #pragma unroll
            for (int i = 0; i < 16; ++i) {
                float4 qq = qrow[i];
                u64t qlo = pack2f(qq.x, qq.y);
                u64t qhi = pack2f(qq.z, qq.w);
                ffma2(a0, qlo, pc2[2*i+0]);
                ffma2(a1, qhi, pc2[2*i+1]);
            }
            float x0, y0, x1, y1;
            unpack2f(a0, x0, y0);
            unpack2f(a1, x1, y1);
            phi_s[g2 * 257 + t] = fmaxf((x0 + y0) + (x1 + y1), 0.0f) + EPS;
        }
        __syncthreads();

        // stage 2: thread computes out[g][td*16 .. td*16+15] and its own d_inv
        u64t acc2[8];
        #pragma unroll
        for (int i = 0; i < 8; ++i) acc2[i] = 0ull;
        float dsum = 0.0f;

        const float* phrow = phi_s + g * 257;
        const float4* c4 = reinterpret_cast<const float4*>(ctx_s);
        #pragma unroll 2
        for (int r = 0; r < RR; ++r) {
            float ph = phrow[r];
            dsum = fmaf(ph, ksum_s[r], dsum);
            u64t ph2 = pack2f(ph, ph);
            #pragma unroll
            for (int i = 0; i < 4; ++i) {
                float4 c = c4[r * 16 + td * 4 + i];
                u64t clo = pack2f(c.x, c.y);
                u64t chi = pack2f(c.z, c.w);
                ffma2(acc2[2*i+0], ph2, clo);
                ffma2(acc2[2*i+1], ph2, chi);
            }
        }
        float rinv = 1.0f / dsum;

        // write output row segment
        {
            float4* O4 = reinterpret_cast<float4*>(Op);
            #pragma unroll
            for (int i = 0; i < 4; ++i) {
                float4 o;
                float x0, y0, x1, y1;
                unpack2f(acc2[2*i+0], x0, y0);
                unpack2f(acc2[2*i+1], x1, y1);
                o.x = x0 * rinv; o.y = y0 * rinv;
                o.z = x1 * rinv; o.w = y1 * rinv;
                O4[(size_t)(tile * 64 + g) * 16 + td * 4 + i] = o;
            }
        }
        __syncthreads();   // protect qs/phi_s before next tile overwrites
    }
}

// ---------------------------------------------------------------------------
// Launch
// ---------------------------------------------------------------------------
extern "C" void kernel_launch(void* const* d_in, const int* in_sizes, int n_in,
                              void* d_out, int out_size)
{
    const float* Q    = (const float*)d_in[0];
    const float* K    = (const float*)d_in[1];
    const float* V    = (const float*)d_in[2];
    const float* mask = (const float*)d_in[3];
    const float* proj = (const float*)d_in[4];
    float* out = (float*)d_out;

    cudaFuncSetAttribute(passB_kernel,
                         cudaFuncAttributeMaxDynamicSharedMemorySize,
                         SMEM_B_BYTES);

    zero_kernel<<<(BH * RR * DD) / 256, 256>>>();
    passA_kernel<<<BH * SPLIT_A, 256>>>(K, V, mask, proj);
    passB_kernel<<<BH * SPLIT_B, 256, SMEM_B_BYTES>>>(Q, proj, out);
}

// round 10
// speedup vs baseline: 4.3804x; 4.1047x over previous
#include <cuda_runtime.h>
#include <cuda_bf16.h>

// Problem constants
#define BB 4
#define HH 8
#define NN 4096
#define DD 64
#define RR 256
#define BH (BB*HH)
#define SCALE 0.35355339059327373f   // 64^(-1/4)
#define EPS 0.001f

#define SPLIT 8                   // CTAs per (b,h)
#define ROWS_CTA (NN/SPLIT)       // 512
#define TILES (ROWS_CTA/128)      // 4

// ctxT scratch: [BH][80][256]  (rows 0..63 = ctx^T (d,feat), row 64 = ksum, 65..79 = 0)
__device__ float g_ctxT[BH * 80 * 256];

// ---------------------------------------------------------------------------
// helpers
// ---------------------------------------------------------------------------
__device__ __forceinline__ unsigned f2tf(float f) {
    unsigned u;
    asm("cvt.rna.tf32.f32 %0, %1;" : "=r"(u) : "f"(f));
    return u;
}

// D += A@B : m16n8k8 tf32, A row-major (4 regs), B col-major (2 regs), D f32 (4 regs)
__device__ __forceinline__ void mma8(float* d, const unsigned* a, const unsigned* b) {
    asm("mma.sync.aligned.m16n8k8.row.col.f32.tf32.tf32.f32 "
        "{%0,%1,%2,%3},{%4,%5,%6,%7},{%8,%9},{%0,%1,%2,%3};"
        : "+f"(d[0]), "+f"(d[1]), "+f"(d[2]), "+f"(d[3])
        : "r"(a[0]), "r"(a[1]), "r"(a[2]), "r"(a[3]), "r"(b[0]), "r"(b[1]));
}

// ---------------------------------------------------------------------------
// zero scratch (graph replays)
// ---------------------------------------------------------------------------
__global__ void zero_kernel() {
    int i = blockIdx.x * blockDim.x + threadIdx.x;
    if (i < BH * 80 * 256) g_ctxT[i] = 0.0f;
}

// ---------------------------------------------------------------------------
// Pass A (tensor): per tile of 128 rows:
//   GEMM1: phi_k[128, fc*64..] = relu((K*m) @ (proj*scale)^T) + eps   (chunks of 64 feats)
//   GEMM2: ctxT[80,256] += V'^T[80,128] @ phi_k[128, chunk]  (V' cols 0-63 = V*m, col 64 = 1)
// smem words: projs 256*68=17408 | km 128*68=8704 | vt 80*132=10560 | phit 64*132=8448
// ---------------------------------------------------------------------------
#define A_SMEM_WORDS (17408 + 8704 + 10560 + 8448)
#define A_SMEM_BYTES (A_SMEM_WORDS * 4)

__global__ void __launch_bounds__(256) passA_tc(
    const float* __restrict__ Kg, const float* __restrict__ Vg,
    const float* __restrict__ maskg, const float* __restrict__ projg)
{
    extern __shared__ unsigned sm[];
    const int S_PROJ = 0;
    const int S_KM   = 17408;
    const int S_VT   = 26112;
    const int S_PHIT = 36672;

    const int t = threadIdx.x;
    const int warp = t >> 5, lane = t & 31;
    const int g = lane >> 2, tq = lane & 3;

    const int bh   = blockIdx.x / SPLIT;
    const int sl   = blockIdx.x % SPLIT;
    const int b    = bh / HH;
    const int row0 = sl * ROWS_CTA;

    // load projs = proj * SCALE (tf32), [feat][d] stride 68  (256*64 = 16384 elems)
    #pragma unroll 4
    for (int i = 0; i < 64; ++i) {
        int e = i * 256 + t;
        int f = e >> 6, d = e & 63;
        sm[S_PROJ + f * 68 + d] = f2tf(projg[e] * SCALE);
    }
    // vt rows 64..79: zero, then row 64 = ones
    for (int i = t; i < 16 * 132; i += 256) sm[S_VT + 64 * 132 + i] = 0u;
    if (t < 128) sm[S_VT + 64 * 132 + t] = __float_as_uint(1.0f);

    // persistent ctxT accumulators: [chunk fc][mi (5x m16)][4]
    float ctxA[4][5][4];
    #pragma unroll
    for (int a = 0; a < 4; ++a)
        #pragma unroll
        for (int m = 0; m < 5; ++m)
            #pragma unroll
            for (int j = 0; j < 4; ++j) ctxA[a][m][j] = 0.0f;

    const int wm = warp >> 1, wn = warp & 1;

    for (int tile = 0; tile < TILES; ++tile) {
        __syncthreads();   // guard km/vt/phit reuse (also covers init on tile 0)

        const float* Kp = Kg + ((size_t)bh * NN + row0 + tile * 128) * 64;
        const float* Vp = Vg + ((size_t)bh * NN + row0 + tile * 128) * 64;
        const float* mp = maskg + (size_t)b * NN + row0 + tile * 128;

        // load tile: km[row][d] = K*m (stride 68); vt[d][row] = V*m transposed (stride 132)
        #pragma unroll 4
        for (int i = 0; i < 32; ++i) {
            int e = i * 256 + t;
            int r = e >> 6, d = e & 63;
            float m = mp[r];
            sm[S_KM + r * 68 + d]  = f2tf(Kp[e] * m);
            sm[S_VT + d * 132 + r] = f2tf(Vp[e] * m);
        }
        __syncthreads();

        #pragma unroll
        for (int fc = 0; fc < 4; ++fc) {
            // ---- GEMM1: phi chunk [128 x 64], warps 4m x 2n, warp tile 32x32 ----
            float acc[2][4][4];
            #pragma unroll
            for (int mi = 0; mi < 2; ++mi)
                #pragma unroll
                for (int ni = 0; ni < 4; ++ni)
                    #pragma unroll
                    for (int j = 0; j < 4; ++j) acc[mi][ni][j] = 0.0f;

            #pragma unroll
            for (int ks = 0; ks < 8; ++ks) {
                int kc = ks * 8 + tq;
                unsigned afr[2][4];
                #pragma unroll
                for (int mi = 0; mi < 2; ++mi) {
                    int r = 32 * wm + 16 * mi + g;
                    const unsigned* p = sm + S_KM + r * 68 + kc;
                    afr[mi][0] = p[0]; afr[mi][1] = p[8 * 68];
                    afr[mi][2] = p[4]; afr[mi][3] = p[8 * 68 + 4];
                }
                #pragma unroll
                for (int ni = 0; ni < 4; ++ni) {
                    int nf = fc * 64 + 32 * wn + 8 * ni + g;
                    const unsigned* p = sm + S_PROJ + nf * 68 + kc;
                    unsigned bfr[2] = { p[0], p[4] };
                    mma8(acc[0][ni], afr[0], bfr);
                    mma8(acc[1][ni], afr[1], bfr);
                }
            }

            // epilogue: relu + eps + cvt, store transposed phit[c][r] (stride 132)
            #pragma unroll
            for (int mi = 0; mi < 2; ++mi)
                #pragma unroll
                for (int ni = 0; ni < 4; ++ni) {
                    int r = 32 * wm + 16 * mi + g;
                    int c = 32 * wn + 8 * ni + 2 * tq;
                    sm[S_PHIT + c       * 132 + r    ] = f2tf(fmaxf(acc[mi][ni][0], 0.f) + EPS);
                    sm[S_PHIT + (c + 1) * 132 + r    ] = f2tf(fmaxf(acc[mi][ni][1], 0.f) + EPS);
                    sm[S_PHIT + c       * 132 + r + 8] = f2tf(fmaxf(acc[mi][ni][2], 0.f) + EPS);
                    sm[S_PHIT + (c + 1) * 132 + r + 8] = f2tf(fmaxf(acc[mi][ni][3], 0.f) + EPS);
                }
            __syncthreads();

            // ---- GEMM2: ctxT[80 x 64chunk] += vt[80,128] @ phit;  warps split n (8 each) ----
            {
                int nb = warp * 8;
                #pragma unroll
                for (int ks = 0; ks < 16; ++ks) {
                    int kc = ks * 8 + tq;
                    const unsigned* pb = sm + S_PHIT + (nb + g) * 132 + kc;
                    unsigned bfr[2] = { pb[0], pb[4] };
                    #pragma unroll
                    for (int mi = 0; mi < 5; ++mi) {
                        int r = 16 * mi + g;
                        const unsigned* pa = sm + S_VT + r * 132 + kc;
                        unsigned afr[4] = { pa[0], pa[8 * 132], pa[4], pa[8 * 132 + 4] };
                        mma8(ctxA[fc][mi], afr, bfr);
                    }
                }
            }
            __syncthreads();   // phit reuse guard
        }
    }

    // write ctxT partials
    #pragma unroll
    for (int fc = 0; fc < 4; ++fc)
        #pragma unroll
        for (int mi = 0; mi < 5; ++mi) {
            int rd = 16 * mi + g;
            int feat = fc * 64 + warp * 8 + 2 * tq;
            float* p0 = g_ctxT + ((size_t)bh * 80 + rd    ) * 256 + feat;
            float* p1 = g_ctxT + ((size_t)bh * 80 + rd + 8) * 256 + feat;
            atomicAdd(p0,     ctxA[fc][mi][0]);
            atomicAdd(p0 + 1, ctxA[fc][mi][1]);
            atomicAdd(p1,     ctxA[fc][mi][2]);
            atomicAdd(p1 + 1, ctxA[fc][mi][3]);
        }
}

// ---------------------------------------------------------------------------
// Pass B (tensor): per tile of 128 rows:
//   GEMM1': phi_q chunk = relu(Q @ projs^T) + eps   -> phiq[row][c] (stride 68)
//   GEMM3 : outraw[128,80] += phi_q @ ctxT^T        (col 64 = denominator)
// smem words: projs 17408 | qs 8704 | phiq 8704 | ctx 80*260=20800 | den 128
// ---------------------------------------------------------------------------
#define B_SMEM_WORDS (17408 + 8704 + 8704 + 20800 + 128)
#define B_SMEM_BYTES (B_SMEM_WORDS * 4)

__global__ void __launch_bounds__(256) passB_tc(
    const float* __restrict__ Qg, const float* __restrict__ projg,
    float* __restrict__ outg)
{
    extern __shared__ unsigned sm[];
    const int S_PROJ = 0;
    const int S_Q    = 17408;
    const int S_PHIQ = 26112;
    const int S_CTX  = 34816;
    const int S_DEN  = 55616;
    float* denS = (float*)(sm + S_DEN);

    const int t = threadIdx.x;
    const int warp = t >> 5, lane = t & 31;
    const int g = lane >> 2, tq = lane & 3;

    const int bh   = blockIdx.x / SPLIT;
    const int sl   = blockIdx.x % SPLIT;
    const int row0 = sl * ROWS_CTA;

    // projs (256*64 = 16384 elems)
    #pragma unroll 4
    for (int i = 0; i < 64; ++i) {
        int e = i * 256 + t;
        int f = e >> 6, d = e & 63;
        sm[S_PROJ + f * 68 + d] = f2tf(projg[e] * SCALE);
    }
    // ctxT [d][feat] stride 260
    #pragma unroll 4
    for (int i = 0; i < 80; ++i) {
        int e = i * 256 + t;
        int d = e >> 8, f = e & 255;
        sm[S_CTX + d * 260 + f] = f2tf(g_ctxT[(size_t)bh * 20480 + e]);
    }

    const int wm = warp >> 1, wn = warp & 1;

    for (int tile = 0; tile < TILES; ++tile) {
        __syncthreads();

        const float* Qp = Qg + ((size_t)bh * NN + row0 + tile * 128) * 64;
        #pragma unroll 4
        for (int i = 0; i < 32; ++i) {
            int e = i * 256 + t;
            int r = e >> 6, d = e & 63;
            sm[S_Q + r * 68 + d] = f2tf(Qp[e]);
        }
        __syncthreads();

        // persistent out accumulators: warp tile 32(m) x 40(n): 2 x 5 frags
        float accO[2][5][4];
        #pragma unroll
        for (int mi = 0; mi < 2; ++mi)
            #pragma unroll
            for (int ni = 0; ni < 5; ++ni)
                #pragma unroll
                for (int j = 0; j < 4; ++j) accO[mi][ni][j] = 0.0f;

        #pragma unroll
        for (int fc = 0; fc < 4; ++fc) {
            // ---- GEMM1': phi_q chunk [128 x 64] ----
            float acc[2][4][4];
            #pragma unroll
            for (int mi = 0; mi < 2; ++mi)
                #pragma unroll
                for (int ni = 0; ni < 4; ++ni)
                    #pragma unroll
                    for (int j = 0; j < 4; ++j) acc[mi][ni][j] = 0.0f;

            #pragma unroll
            for (int ks = 0; ks < 8; ++ks) {
                int kc = ks * 8 + tq;
                unsigned afr[2][4];
                #pragma unroll
                for (int mi = 0; mi < 2; ++mi) {
                    int r = 32 * wm + 16 * mi + g;
                    const unsigned* p = sm + S_Q + r * 68 + kc;
                    afr[mi][0] = p[0]; afr[mi][1] = p[8 * 68];
                    afr[mi][2] = p[4]; afr[mi][3] = p[8 * 68 + 4];
                }
                #pragma unroll
                for (int ni = 0; ni < 4; ++ni) {
                    int nf = fc * 64 + 32 * wn + 8 * ni + g;
                    const unsigned* p = sm + S_PROJ + nf * 68 + kc;
                    unsigned bfr[2] = { p[0], p[4] };
                    mma8(acc[0][ni], afr[0], bfr);
                    mma8(acc[1][ni], afr[1], bfr);
                }
            }
            // store phiq[row][c] (chunk-local, stride 68)
            #pragma unroll
            for (int mi = 0; mi < 2; ++mi)
                #pragma unroll
                for (int ni = 0; ni < 4; ++ni) {
                    int r = 32 * wm + 16 * mi + g;
                    int c = 32 * wn + 8 * ni + 2 * tq;
                    sm[S_PHIQ + r       * 68 + c    ] = f2tf(fmaxf(acc[mi][ni][0], 0.f) + EPS);
                    sm[S_PHIQ + r       * 68 + c + 1] = f2tf(fmaxf(acc[mi][ni][1], 0.f) + EPS);
                    sm[S_PHIQ + (r + 8) * 68 + c    ] = f2tf(fmaxf(acc[mi][ni][2], 0.f) + EPS);
                    sm[S_PHIQ + (r + 8) * 68 + c + 1] = f2tf(fmaxf(acc[mi][ni][3], 0.f) + EPS);
                }
            __syncthreads();

            // ---- GEMM3 partial: outraw += phiq @ ctxT^T  (k = 64 chunk feats) ----
            #pragma unroll
            for (int ks = 0; ks < 8; ++ks) {
                int kc = ks * 8 + tq;
                unsigned afr[2][4];
                #pragma unroll
                for (int mi = 0; mi < 2; ++mi) {
                    int r = 32 * wm + 16 * mi + g;
                    const unsigned* p = sm + S_PHIQ + r * 68 + kc;
                    afr[mi][0] = p[0]; afr[mi][1] = p[8 * 68];
                    afr[mi][2] = p[4]; afr[mi][3] = p[8 * 68 + 4];
                }
                #pragma unroll
                for (int ni = 0; ni < 5; ++ni) {
                    int n = 40 * wn + 8 * ni + g;
                    const unsigned* p = sm + S_CTX + n * 260 + fc * 64 + kc;
                    unsigned bfr[2] = { p[0], p[4] };
                    mma8(accO[0][ni], afr[0], bfr);
                    mma8(accO[1][ni], afr[1], bfr);
                }
            }
            __syncthreads();   // phiq reuse guard
        }

        // denominator: col 64 lives in warps wn==1, frag ni=3, lanes tq==0, element 0/2
        if (wn == 1 && tq == 0) {
            #pragma unroll
            for (int mi = 0; mi < 2; ++mi) {
                int r = 32 * wm + 16 * mi + g;
                denS[r]     = accO[mi][3][0];
                denS[r + 8] = accO[mi][3][2];
            }
        }
        __syncthreads();

        // scaled store
        float* Op = outg + ((size_t)bh * NN + row0 + tile * 128) * 64;
        #pragma unroll
        for (int mi = 0; mi < 2; ++mi) {
            int r = 32 * wm + 16 * mi + g;
            float ri0 = 1.0f / denS[r];
            float ri1 = 1.0f / denS[r + 8];
            #pragma unroll
            for (int ni = 0; ni < 5; ++ni) {
                int c = 40 * wn + 8 * ni + 2 * tq;
                if (c < 64) {
                    float2 o0 = { accO[mi][ni][0] * ri0, accO[mi][ni][1] * ri0 };
                    float2 o1 = { accO[mi][ni][2] * ri1, accO[mi][ni][3] * ri1 };
                    *reinterpret_cast<float2*>(Op + (size_t)r * 64 + c)       = o0;
                    *reinterpret_cast<float2*>(Op + (size_t)(r + 8) * 64 + c) = o1;
                }
            }
        }
    }
}

// ---------------------------------------------------------------------------
// Launch
// ---------------------------------------------------------------------------
extern "C" void kernel_launch(void* const* d_in, const int* in_sizes, int n_in,
                              void* d_out, int out_size)
{
    const float* Q    = (const float*)d_in[0];
    const float* K    = (const float*)d_in[1];
    const float* V    = (const float*)d_in[2];
    const float* mask = (const float*)d_in[3];
    const float* proj = (const float*)d_in[4];
    float* out = (float*)d_out;

    cudaFuncSetAttribute(passA_tc, cudaFuncAttributeMaxDynamicSharedMemorySize, A_SMEM_BYTES);
    cudaFuncSetAttribute(passB_tc, cudaFuncAttributeMaxDynamicSharedMemorySize, B_SMEM_BYTES);

    zero_kernel<<<(BH * 80 * 256) / 256, 256>>>();
    passA_tc<<<BH * SPLIT, 256, A_SMEM_BYTES>>>(K, V, mask, proj);
    passB_tc<<<BH * SPLIT, 256, B_SMEM_BYTES>>>(Q, proj, out);
}